// round 1
// baseline (speedup 1.0000x reference)
#include <cuda_runtime.h>
#include <math.h>

#define HIDDEN 1152
#define HEADS  16
#define HD     72
#define BATCH  16
#define SEQ    1024
#define M_TOT  (BATCH*SEQ)        // 16384
#define N_QKV  (3*HIDDEN)         // 3456
#define QSCALE 0.11785113f        // 1/sqrt(72)
#define RMS_EPS 1.1920928955078125e-07f

// ---------------- scratch (no cudaMalloc allowed) ----------------
__device__ float g_q[(size_t)BATCH*HEADS*SEQ*HD];     // [B,H,S,D]
__device__ float g_k[(size_t)BATCH*HEADS*SEQ*HD];
__device__ float g_v[(size_t)BATCH*HEADS*SEQ*HD];
__device__ float g_attn[(size_t)BATCH*SEQ*HIDDEN];    // [B,S,H*D]

// ---------------- SGEMM: C[M,N] = A[M,K] * W[N,K]^T ----------------
#define BM 128
#define BN 128
#define BK 16

// QKV GEMM: x[16384,1152] @ w_qkv[3456,1152]^T + b -> scatter into g_q/g_k/g_v [B,H,S,D]
__global__ __launch_bounds__(256) void gemm_qkv_kernel(const float* __restrict__ x,
                                                       const float* __restrict__ w,
                                                       const float* __restrict__ bias) {
    __shared__ float As[BK][BM];
    __shared__ float Bs[BK][BN];
    const int tid = threadIdx.x;
    const int tr = tid >> 4;          // 0..15
    const int tc = tid & 15;          // 0..15
    const int m0 = blockIdx.y * BM;
    const int n0 = blockIdx.x * BN;
    const int lr = tid >> 2;          // 0..63
    const int lk = (tid & 3) << 2;    // 0,4,8,12

    const float* Ap = x + (size_t)(m0 + lr) * HIDDEN + lk;
    const float* Bp = w + (size_t)(n0 + lr) * HIDDEN + lk;

    float acc[8][8];
#pragma unroll
    for (int i = 0; i < 8; ++i)
#pragma unroll
        for (int j = 0; j < 8; ++j) acc[i][j] = 0.f;

    for (int kt = 0; kt < HIDDEN; kt += BK) {
        float4 a0 = *(const float4*)(Ap);
        float4 a1 = *(const float4*)(Ap + (size_t)64 * HIDDEN);
        float4 b0 = *(const float4*)(Bp);
        float4 b1 = *(const float4*)(Bp + (size_t)64 * HIDDEN);
        __syncthreads();
        As[lk+0][lr]    = a0.x; As[lk+1][lr]    = a0.y; As[lk+2][lr]    = a0.z; As[lk+3][lr]    = a0.w;
        As[lk+0][lr+64] = a1.x; As[lk+1][lr+64] = a1.y; As[lk+2][lr+64] = a1.z; As[lk+3][lr+64] = a1.w;
        Bs[lk+0][lr]    = b0.x; Bs[lk+1][lr]    = b0.y; Bs[lk+2][lr]    = b0.z; Bs[lk+3][lr]    = b0.w;
        Bs[lk+0][lr+64] = b1.x; Bs[lk+1][lr+64] = b1.y; Bs[lk+2][lr+64] = b1.z; Bs[lk+3][lr+64] = b1.w;
        __syncthreads();
        const float4* As4 = (const float4*)&As[0][0];  // [16][32]
        const float4* Bs4 = (const float4*)&Bs[0][0];
#pragma unroll
        for (int kk = 0; kk < BK; ++kk) {
            float4 A0 = As4[kk*32 + tr*2];
            float4 A1 = As4[kk*32 + tr*2 + 1];
            float4 B0 = Bs4[kk*32 + tc*2];
            float4 B1 = Bs4[kk*32 + tc*2 + 1];
            float av[8] = {A0.x,A0.y,A0.z,A0.w,A1.x,A1.y,A1.z,A1.w};
            float bv[8] = {B0.x,B0.y,B0.z,B0.w,B1.x,B1.y,B1.z,B1.w};
#pragma unroll
            for (int i = 0; i < 8; ++i)
#pragma unroll
                for (int j = 0; j < 8; ++j) acc[i][j] += av[i]*bv[j];
        }
        Ap += BK;
        Bp += BK;
    }

    // epilogue: scatter to q/k/v in [B,H,S,D]; block is entirely inside one of q/k/v (1152 = 9*128)
    const int which = n0 / HIDDEN;
    float* dst = (which == 0) ? g_q : (which == 1) ? g_k : g_v;
#pragma unroll
    for (int j = 0; j < 8; ++j) {
        const int col = n0 + tc*8 + j;
        const int rem = col - which*HIDDEN;
        const int h   = rem / HD;
        const int d   = rem - h*HD;
        const float bc = bias[col];
#pragma unroll
        for (int i = 0; i < 8; ++i) {
            const int row = m0 + tr*8 + i;
            const int bi  = row >> 10;          // /1024
            const int si  = row & (SEQ-1);
            dst[(((size_t)(bi*HEADS + h))*SEQ + si)*HD + d] = acc[i][j] + bc;
        }
    }
}

// proj GEMM: g_attn[16384,1152] @ w_proj[1152,1152]^T + b -> out
__global__ __launch_bounds__(256) void gemm_proj_kernel(const float* __restrict__ w,
                                                        const float* __restrict__ bias,
                                                        float* __restrict__ out) {
    __shared__ float As[BK][BM];
    __shared__ float Bs[BK][BN];
    const int tid = threadIdx.x;
    const int tr = tid >> 4;
    const int tc = tid & 15;
    const int m0 = blockIdx.y * BM;
    const int n0 = blockIdx.x * BN;
    const int lr = tid >> 2;
    const int lk = (tid & 3) << 2;

    const float* Ap = g_attn + (size_t)(m0 + lr) * HIDDEN + lk;
    const float* Bp = w + (size_t)(n0 + lr) * HIDDEN + lk;

    float acc[8][8];
#pragma unroll
    for (int i = 0; i < 8; ++i)
#pragma unroll
        for (int j = 0; j < 8; ++j) acc[i][j] = 0.f;

    for (int kt = 0; kt < HIDDEN; kt += BK) {
        float4 a0 = *(const float4*)(Ap);
        float4 a1 = *(const float4*)(Ap + (size_t)64 * HIDDEN);
        float4 b0 = *(const float4*)(Bp);
        float4 b1 = *(const float4*)(Bp + (size_t)64 * HIDDEN);
        __syncthreads();
        As[lk+0][lr]    = a0.x; As[lk+1][lr]    = a0.y; As[lk+2][lr]    = a0.z; As[lk+3][lr]    = a0.w;
        As[lk+0][lr+64] = a1.x; As[lk+1][lr+64] = a1.y; As[lk+2][lr+64] = a1.z; As[lk+3][lr+64] = a1.w;
        Bs[lk+0][lr]    = b0.x; Bs[lk+1][lr]    = b0.y; Bs[lk+2][lr]    = b0.z; Bs[lk+3][lr]    = b0.w;
        Bs[lk+0][lr+64] = b1.x; Bs[lk+1][lr+64] = b1.y; Bs[lk+2][lr+64] = b1.z; Bs[lk+3][lr+64] = b1.w;
        __syncthreads();
        const float4* As4 = (const float4*)&As[0][0];
        const float4* Bs4 = (const float4*)&Bs[0][0];
#pragma unroll
        for (int kk = 0; kk < BK; ++kk) {
            float4 A0 = As4[kk*32 + tr*2];
            float4 A1 = As4[kk*32 + tr*2 + 1];
            float4 B0 = Bs4[kk*32 + tc*2];
            float4 B1 = Bs4[kk*32 + tc*2 + 1];
            float av[8] = {A0.x,A0.y,A0.z,A0.w,A1.x,A1.y,A1.z,A1.w};
            float bv[8] = {B0.x,B0.y,B0.z,B0.w,B1.x,B1.y,B1.z,B1.w};
#pragma unroll
            for (int i = 0; i < 8; ++i)
#pragma unroll
                for (int j = 0; j < 8; ++j) acc[i][j] += av[i]*bv[j];
        }
        Ap += BK;
        Bp += BK;
    }

#pragma unroll
    for (int j = 0; j < 8; ++j) {
        const int col = n0 + tc*8 + j;
        const float bc = bias[col];
#pragma unroll
        for (int i = 0; i < 8; ++i) {
            const int row = m0 + tr*8 + i;
            out[(size_t)row * HIDDEN + col] = acc[i][j] + bc;
        }
    }
}

// ---------------- RMSNorm over head_dim=72, one warp per row ----------------
__global__ __launch_bounds__(256) void rmsnorm_kernel(int sel, const float* __restrict__ gamma) {
    float* t = sel ? g_k : g_q;
    const int row  = blockIdx.x * 8 + (threadIdx.x >> 5);
    const int lane = threadIdx.x & 31;
    float* p = t + (size_t)row * HD;
    float v0 = p[lane];
    float v1 = p[32 + lane];
    float v2 = (lane < 8) ? p[64 + lane] : 0.f;
    float ss = v0*v0 + v1*v1 + v2*v2;
#pragma unroll
    for (int o = 16; o; o >>= 1) ss += __shfl_xor_sync(0xffffffffu, ss, o);
    const float rs = rsqrtf(ss * (1.0f/72.0f) + RMS_EPS);
    p[lane]      = v0 * rs * gamma[lane];
    p[32 + lane] = v1 * rs * gamma[32 + lane];
    if (lane < 8) p[64 + lane] = v2 * rs * gamma[64 + lane];
}

// ---------------- flash attention: 1 CTA per (b, h, 64-query tile) ----------------
// smem: Qs[64][72] Ks[64][72] Vs[64][72] Ps[64][64]  => 71680 bytes dynamic
#define ATTN_SMEM ((3*64*72 + 64*64)*4)

__global__ __launch_bounds__(256) void attn_kernel() {
    extern __shared__ float sm[];
    float* Qs = sm;                 // 64*72
    float* Ks = sm + 4608;          // 64*72
    float* Vs = sm + 9216;          // 64*72
    float* Ps = sm + 13824;         // 64*64

    const int qt = blockIdx.x;      // 0..15
    const int h  = blockIdx.y;      // 0..15
    const int b  = blockIdx.z;      // 0..15
    const int tid  = threadIdx.x;
    const int r    = tid >> 2;      // 0..63 query row in tile
    const int sub  = tid & 3;       // 0..3

    const size_t head_base = ((size_t)(b*HEADS + h)) * SEQ * HD;
    const size_t q_base = head_base + (size_t)qt * 64 * HD;

    // load Q tile, pre-scaled by 1/sqrt(HD)
    for (int idx = tid; idx < 64*HD; idx += 256)
        Qs[idx] = g_q[q_base + idx] * QSCALE;

    float m = -INFINITY, l = 0.f;
    float acc[18];
#pragma unroll
    for (int d = 0; d < 18; ++d) acc[d] = 0.f;

    for (int kt = 0; kt < SEQ/64; ++kt) {
        __syncthreads();   // prior-tile Ps/Vs consumers done
        const size_t kv_base = head_base + (size_t)kt * 64 * HD;
        for (int idx = tid; idx < 64*HD; idx += 256) {
            Ks[idx] = g_k[kv_base + idx];
            Vs[idx] = g_v[kv_base + idx];
        }
        __syncthreads();

        // scores: this thread handles keys j = sub*16 + jj
        float sc[16];
        const float4* qrow = (const float4*)(Qs + r*HD);
#pragma unroll
        for (int jj = 0; jj < 16; ++jj) {
            const int j = sub*16 + jj;
            const float4* krow = (const float4*)(Ks + j*HD);
            float s = 0.f;
#pragma unroll
            for (int dd = 0; dd < 18; ++dd) {
                float4 qa = qrow[dd];
                float4 ka = krow[dd];
                s += qa.x*ka.x + qa.y*ka.y + qa.z*ka.z + qa.w*ka.w;
            }
            sc[jj] = s;
        }

        // tile row-max across the 4 subs (lanes r*4..r*4+3 are aligned within warp)
        float tmax = sc[0];
#pragma unroll
        for (int jj = 1; jj < 16; ++jj) tmax = fmaxf(tmax, sc[jj]);
        tmax = fmaxf(tmax, __shfl_xor_sync(0xffffffffu, tmax, 1));
        tmax = fmaxf(tmax, __shfl_xor_sync(0xffffffffu, tmax, 2));

        const float m_new = fmaxf(m, tmax);
        const float fac = __expf(m - m_new);   // exp(-inf) = 0 on first tile

        float psum = 0.f;
#pragma unroll
        for (int jj = 0; jj < 16; ++jj) {
            const float p = __expf(sc[jj] - m_new);
            Ps[r*64 + sub*16 + jj] = p;
            psum += p;
        }
        psum += __shfl_xor_sync(0xffffffffu, psum, 1);
        psum += __shfl_xor_sync(0xffffffffu, psum, 2);

        l = l * fac + psum;
        m = m_new;
#pragma unroll
        for (int d = 0; d < 18; ++d) acc[d] *= fac;

        __syncthreads();   // Ps fully written

        // PV: acc[d] += sum_j P[r][j] * V[j][sub*18 + d]
        for (int j = 0; j < 64; ++j) {
            const float pj = Ps[r*64 + j];
            const float2* vrow = (const float2*)(Vs + j*HD + sub*18);
#pragma unroll
            for (int dd = 0; dd < 9; ++dd) {
                float2 vv = vrow[dd];
                acc[2*dd]   += pj * vv.x;
                acc[2*dd+1] += pj * vv.y;
            }
        }
    }

    const float inv_l = 1.0f / l;
    const int qrow_g = qt*64 + r;
    float* op = g_attn + (((size_t)(b*SEQ + qrow_g))*HEADS + h)*HD + sub*18;
#pragma unroll
    for (int dd = 0; dd < 18; ++dd) op[dd] = acc[dd] * inv_l;
}

// ---------------- launch ----------------
extern "C" void kernel_launch(void* const* d_in, const int* in_sizes, int n_in,
                              void* d_out, int out_size) {
    const float* x      = (const float*)d_in[0];
    const float* w_qkv  = (const float*)d_in[1];
    const float* b_qkv  = (const float*)d_in[2];
    const float* q_gamma= (const float*)d_in[3];
    const float* k_gamma= (const float*)d_in[4];
    const float* w_proj = (const float*)d_in[5];
    const float* b_proj = (const float*)d_in[6];
    float* out = (float*)d_out;

    cudaFuncSetAttribute(attn_kernel, cudaFuncAttributeMaxDynamicSharedMemorySize, ATTN_SMEM);

    {   // QKV projection
        dim3 grid(N_QKV / BN, M_TOT / BM);   // (27, 128)
        gemm_qkv_kernel<<<grid, 256>>>(x, w_qkv, b_qkv);
    }
    {   // RMSNorm on q and k (262144 rows each, 8 rows/block)
        const int rows = BATCH*HEADS*SEQ;
        rmsnorm_kernel<<<rows/8, 256>>>(0, q_gamma);
        rmsnorm_kernel<<<rows/8, 256>>>(1, k_gamma);
    }
    {   // attention
        dim3 grid(SEQ/64, HEADS, BATCH);     // (16,16,16)
        attn_kernel<<<grid, 256, ATTN_SMEM>>>();
    }
    {   // output projection
        dim3 grid(HIDDEN / BN, M_TOT / BM);  // (9, 128)
        gemm_proj_kernel<<<grid, 256>>>(w_proj, b_proj, out);
    }
}

// round 2
// speedup vs baseline: 1.2404x; 1.2404x over previous
#include <cuda_runtime.h>
#include <math.h>

#define HIDDEN 1152
#define HEADS  16
#define HD     72
#define BATCH  16
#define SEQ    1024
#define M_TOT  (BATCH*SEQ)        // 16384
#define N_QKV  (3*HIDDEN)         // 3456
#define QSCALE 0.11785113f        // 1/sqrt(72)
#define RMS_EPS 1.1920928955078125e-07f

// ---------------- scratch (no cudaMalloc allowed) ----------------
__device__ float g_q[(size_t)BATCH*HEADS*SEQ*HD];     // [B,H,S,D]
__device__ float g_k[(size_t)BATCH*HEADS*SEQ*HD];
__device__ float g_v[(size_t)BATCH*HEADS*SEQ*HD];
__device__ float g_attn[(size_t)BATCH*SEQ*HIDDEN];    // [B,S,H*D]

// =======================================================================
// tf32 tensor-core GEMM:  C[M,N] = A[M,K] * W[N,K]^T + bias
// BM=128 BN=128 BK=32, 256 threads = 8 warps (2x4), warp tile 64x32
// mma.sync.aligned.m16n8k8.row.col.f32.tf32.tf32.f32
// =======================================================================
#define GBM 128
#define GBN 128
#define GBK 32
#define LDS_STRIDE 36   // 32 + 4 pad words: row step = 4 banks, conflict-free frags

__device__ __forceinline__ unsigned f2tf32(float f) {
    unsigned u;
    asm("cvt.rna.tf32.f32 %0, %1;" : "=r"(u) : "f"(f));
    return u;
}

__device__ __forceinline__ void mma_tf32(float c[4], const unsigned a[4], const unsigned b[2]) {
    asm volatile(
        "mma.sync.aligned.m16n8k8.row.col.f32.tf32.tf32.f32 "
        "{%0,%1,%2,%3},{%4,%5,%6,%7},{%8,%9},{%0,%1,%2,%3};"
        : "+f"(c[0]), "+f"(c[1]), "+f"(c[2]), "+f"(c[3])
        : "r"(a[0]), "r"(a[1]), "r"(a[2]), "r"(a[3]), "r"(b[0]), "r"(b[1]));
}

// mode 0: QKV (N=3456) -> scatter into g_q/g_k/g_v [B,H,S,D]
// mode 1: proj (N=1152) -> out row-major
__global__ __launch_bounds__(256) void gemm_tf32_kernel(const float* __restrict__ A,
                                                        const float* __restrict__ W,
                                                        const float* __restrict__ bias,
                                                        float* __restrict__ out,
                                                        int mode) {
    __shared__ unsigned As[GBM * LDS_STRIDE];
    __shared__ unsigned Bs[GBN * LDS_STRIDE];

    const int tid  = threadIdx.x;
    const int warp = tid >> 5;
    const int wr   = warp >> 2;        // 0..1
    const int wc   = warp & 3;         // 0..3
    const int lane = tid & 31;
    const int gid  = lane >> 2;        // 0..7
    const int tidg = lane & 3;         // 0..3

    const int m0 = blockIdx.y * GBM;
    const int n0 = blockIdx.x * GBN;

    // gmem->smem copy mapping: 8 threads per row (float4 each), 32 rows/pass, 4 passes
    const int crow = tid >> 3;         // 0..31
    const int ccol = (tid & 7) * 4;    // 0,4,...,28

    float acc[4][4][4];
#pragma unroll
    for (int mi = 0; mi < 4; ++mi)
#pragma unroll
        for (int ni = 0; ni < 4; ++ni)
#pragma unroll
            for (int r = 0; r < 4; ++r) acc[mi][ni][r] = 0.f;

    for (int kt = 0; kt < HIDDEN; kt += GBK) {
        __syncthreads();
#pragma unroll
        for (int p = 0; p < 4; ++p) {
            const int row = crow + p * 32;
            float4 va = *(const float4*)(A + (size_t)(m0 + row) * HIDDEN + kt + ccol);
            float4 vb = *(const float4*)(W + (size_t)(n0 + row) * HIDDEN + kt + ccol);
            uint4 ua = make_uint4(f2tf32(va.x), f2tf32(va.y), f2tf32(va.z), f2tf32(va.w));
            uint4 ub = make_uint4(f2tf32(vb.x), f2tf32(vb.y), f2tf32(vb.z), f2tf32(vb.w));
            *(uint4*)&As[row * LDS_STRIDE + ccol] = ua;
            *(uint4*)&Bs[row * LDS_STRIDE + ccol] = ub;
        }
        __syncthreads();

#pragma unroll
        for (int ks = 0; ks < GBK / 8; ++ks) {
            unsigned a[4][4];
#pragma unroll
            for (int mi = 0; mi < 4; ++mi) {
                const int base = (wr * 64 + mi * 16 + gid) * LDS_STRIDE + ks * 8 + tidg;
                a[mi][0] = As[base];
                a[mi][1] = As[base + 8 * LDS_STRIDE];
                a[mi][2] = As[base + 4];
                a[mi][3] = As[base + 8 * LDS_STRIDE + 4];
            }
            unsigned b[4][2];
#pragma unroll
            for (int ni = 0; ni < 4; ++ni) {
                const int base = (wc * 32 + ni * 8 + gid) * LDS_STRIDE + ks * 8 + tidg;
                b[ni][0] = Bs[base];
                b[ni][1] = Bs[base + 4];
            }
#pragma unroll
            for (int mi = 0; mi < 4; ++mi)
#pragma unroll
                for (int ni = 0; ni < 4; ++ni)
                    mma_tf32(acc[mi][ni], a[mi], b[ni]);
        }
    }

    // ---------------- epilogue ----------------
    if (mode == 0) {
        // QKV scatter. 1152 % 128 == 0 so one block maps to exactly one of q/k/v
        const int which = n0 / HIDDEN;
        float* dst = (which == 0) ? g_q : (which == 1) ? g_k : g_v;
#pragma unroll
        for (int mi = 0; mi < 4; ++mi)
#pragma unroll
            for (int ni = 0; ni < 4; ++ni)
#pragma unroll
                for (int cr = 0; cr < 4; ++cr) {
                    const int row = m0 + wr * 64 + mi * 16 + gid + (cr >> 1) * 8;
                    const int col = n0 + wc * 32 + ni * 8 + 2 * tidg + (cr & 1);
                    const int rem = col - which * HIDDEN;
                    const int h   = rem / HD;
                    const int d   = rem - h * HD;
                    const int bi  = row >> 10;
                    const int si  = row & (SEQ - 1);
                    dst[(((size_t)(bi * HEADS + h)) * SEQ + si) * HD + d] =
                        acc[mi][ni][cr] + bias[col];
                }
    } else {
#pragma unroll
        for (int mi = 0; mi < 4; ++mi)
#pragma unroll
            for (int ni = 0; ni < 4; ++ni)
#pragma unroll
                for (int cr = 0; cr < 4; ++cr) {
                    const int row = m0 + wr * 64 + mi * 16 + gid + (cr >> 1) * 8;
                    const int col = n0 + wc * 32 + ni * 8 + 2 * tidg + (cr & 1);
                    out[(size_t)row * HIDDEN + col] = acc[mi][ni][cr] + bias[col];
                }
    }
}

// ---------------- RMSNorm over head_dim=72, one warp per row ----------------
__global__ __launch_bounds__(256) void rmsnorm_kernel(int sel, const float* __restrict__ gamma) {
    float* t = sel ? g_k : g_q;
    const int row  = blockIdx.x * 8 + (threadIdx.x >> 5);
    const int lane = threadIdx.x & 31;
    float* p = t + (size_t)row * HD;
    float v0 = p[lane];
    float v1 = p[32 + lane];
    float v2 = (lane < 8) ? p[64 + lane] : 0.f;
    float ss = v0*v0 + v1*v1 + v2*v2;
#pragma unroll
    for (int o = 16; o; o >>= 1) ss += __shfl_xor_sync(0xffffffffu, ss, o);
    const float rs = rsqrtf(ss * (1.0f/72.0f) + RMS_EPS);
    p[lane]      = v0 * rs * gamma[lane];
    p[32 + lane] = v1 * rs * gamma[32 + lane];
    if (lane < 8) p[64 + lane] = v2 * rs * gamma[64 + lane];
}

// ---------------- flash attention: 1 CTA per (b, h, 64-query tile) ----------------
// smem: Qs[64][72] Ks[64][72] Vs[64][72] Ps[64][64]  => 71680 bytes dynamic
#define ATTN_SMEM ((3*64*72 + 64*64)*4)

__global__ __launch_bounds__(256) void attn_kernel() {
    extern __shared__ float sm[];
    float* Qs = sm;                 // 64*72
    float* Ks = sm + 4608;          // 64*72
    float* Vs = sm + 9216;          // 64*72
    float* Ps = sm + 13824;         // 64*64

    const int qt = blockIdx.x;      // 0..15
    const int h  = blockIdx.y;      // 0..15
    const int b  = blockIdx.z;      // 0..15
    const int tid  = threadIdx.x;
    const int r    = tid >> 2;      // 0..63 query row in tile
    const int sub  = tid & 3;       // 0..3

    const size_t head_base = ((size_t)(b*HEADS + h)) * SEQ * HD;
    const size_t q_base = head_base + (size_t)qt * 64 * HD;

    // load Q tile, pre-scaled by 1/sqrt(HD)
    for (int idx = tid; idx < 64*HD; idx += 256)
        Qs[idx] = g_q[q_base + idx] * QSCALE;

    float m = -INFINITY, l = 0.f;
    float acc[18];
#pragma unroll
    for (int d = 0; d < 18; ++d) acc[d] = 0.f;

    for (int kt = 0; kt < SEQ/64; ++kt) {
        __syncthreads();   // prior-tile Ps/Vs consumers done
        const size_t kv_base = head_base + (size_t)kt * 64 * HD;
        for (int idx = tid; idx < 64*HD; idx += 256) {
            Ks[idx] = g_k[kv_base + idx];
            Vs[idx] = g_v[kv_base + idx];
        }
        __syncthreads();

        // scores: dd-outer / jj-inner so each Q float4 is read ONCE per tile
        float sc[16];
#pragma unroll
        for (int jj = 0; jj < 16; ++jj) sc[jj] = 0.f;
        const float4* qrow = (const float4*)(Qs + r*HD);
        const float4* kbase = (const float4*)(Ks + (sub*16)*HD);
#pragma unroll
        for (int dd = 0; dd < 18; ++dd) {
            const float4 qa = qrow[dd];
#pragma unroll
            for (int jj = 0; jj < 16; ++jj) {
                const float4 ka = kbase[jj*18 + dd];
                sc[jj] += qa.x*ka.x + qa.y*ka.y + qa.z*ka.z + qa.w*ka.w;
            }
        }

        // tile row-max across the 4 subs (lanes r*4..r*4+3 are aligned within warp)
        float tmax = sc[0];
#pragma unroll
        for (int jj = 1; jj < 16; ++jj) tmax = fmaxf(tmax, sc[jj]);
        tmax = fmaxf(tmax, __shfl_xor_sync(0xffffffffu, tmax, 1));
        tmax = fmaxf(tmax, __shfl_xor_sync(0xffffffffu, tmax, 2));

        const float m_new = fmaxf(m, tmax);
        const float fac = __expf(m - m_new);   // exp(-inf) = 0 on first tile

        float psum = 0.f;
#pragma unroll
        for (int jj = 0; jj < 16; ++jj) {
            const float p = __expf(sc[jj] - m_new);
            Ps[r*64 + sub*16 + jj] = p;
            psum += p;
        }
        psum += __shfl_xor_sync(0xffffffffu, psum, 1);
        psum += __shfl_xor_sync(0xffffffffu, psum, 2);

        l = l * fac + psum;
        m = m_new;
#pragma unroll
        for (int d = 0; d < 18; ++d) acc[d] *= fac;

        __syncthreads();   // Ps fully written

        // PV: acc[d] += sum_j P[r][j] * V[j][sub*18 + d]
        for (int j = 0; j < 64; ++j) {
            const float pj = Ps[r*64 + j];
            const float2* vrow = (const float2*)(Vs + j*HD + sub*18);
#pragma unroll
            for (int dd = 0; dd < 9; ++dd) {
                float2 vv = vrow[dd];
                acc[2*dd]   += pj * vv.x;
                acc[2*dd+1] += pj * vv.y;
            }
        }
    }

    const float inv_l = 1.0f / l;
    const int qrow_g = qt*64 + r;
    float* op = g_attn + (((size_t)(b*SEQ + qrow_g))*HEADS + h)*HD + sub*18;
#pragma unroll
    for (int dd = 0; dd < 18; ++dd) op[dd] = acc[dd] * inv_l;
}

// ---------------- launch ----------------
extern "C" void kernel_launch(void* const* d_in, const int* in_sizes, int n_in,
                              void* d_out, int out_size) {
    const float* x      = (const float*)d_in[0];
    const float* w_qkv  = (const float*)d_in[1];
    const float* b_qkv  = (const float*)d_in[2];
    const float* q_gamma= (const float*)d_in[3];
    const float* k_gamma= (const float*)d_in[4];
    const float* w_proj = (const float*)d_in[5];
    const float* b_proj = (const float*)d_in[6];
    float* out = (float*)d_out;

    cudaFuncSetAttribute(attn_kernel, cudaFuncAttributeMaxDynamicSharedMemorySize, ATTN_SMEM);

    // device globals as raw pointers for the proj GEMM A-operand
    float* attn_ptr = nullptr;
    cudaGetSymbolAddress((void**)&attn_ptr, g_attn);

    {   // QKV projection (tf32 tensor cores)
        dim3 grid(N_QKV / GBN, M_TOT / GBM);   // (27, 128)
        gemm_tf32_kernel<<<grid, 256>>>(x, w_qkv, b_qkv, nullptr, 0);
    }
    {   // RMSNorm on q and k (262144 rows each, 8 rows/block)
        const int rows = BATCH*HEADS*SEQ;
        rmsnorm_kernel<<<rows/8, 256>>>(0, q_gamma);
        rmsnorm_kernel<<<rows/8, 256>>>(1, k_gamma);
    }
    {   // attention
        dim3 grid(SEQ/64, HEADS, BATCH);       // (16,16,16)
        attn_kernel<<<grid, 256, ATTN_SMEM>>>();
    }
    {   // output projection (tf32 tensor cores)
        dim3 grid(HIDDEN / GBN, M_TOT / GBM);  // (9, 128)
        gemm_tf32_kernel<<<grid, 256>>>(attn_ptr, w_proj, b_proj, out, 1);
    }
}

// round 3
// speedup vs baseline: 7.7218x; 6.2252x over previous
#include <cuda_runtime.h>
#include <math.h>

#define HIDDEN 1152
#define HEADS  16
#define HD     72
#define BATCH  16
#define SEQ    1024
#define M_TOT  (BATCH*SEQ)        // 16384
#define N_QKV  (3*HIDDEN)         // 3456
#define QSCALE 0.11785113f        // 1/sqrt(72)
#define RMS_EPS 1.1920928955078125e-07f

// ---------------- scratch (no cudaMalloc allowed) ----------------
__device__ float g_q[(size_t)BATCH*HEADS*SEQ*HD];     // [B,H,S,D]
__device__ float g_k[(size_t)BATCH*HEADS*SEQ*HD];
__device__ float g_v[(size_t)BATCH*HEADS*SEQ*HD];
__device__ float g_attn[(size_t)BATCH*SEQ*HIDDEN];    // [B,S,H*D] (tf32-rounded)
__device__ float g_xt[(size_t)M_TOT*HIDDEN];          // x rounded to tf32
__device__ float g_wq[(size_t)N_QKV*HIDDEN];          // w_qkv rounded
__device__ float g_wp[(size_t)HIDDEN*HIDDEN];         // w_proj rounded

// ---------------- helpers ----------------
__device__ __forceinline__ unsigned f2tf32(float f) {
    unsigned u;
    asm("cvt.rna.tf32.f32 %0, %1;" : "=r"(u) : "f"(f));
    return u;
}
__device__ __forceinline__ float tf32r(float f) { return __uint_as_float(f2tf32(f)); }

__device__ __forceinline__ void mma_tf32(float c[4], const unsigned a[4], const unsigned b[2]) {
    asm volatile(
        "mma.sync.aligned.m16n8k8.row.col.f32.tf32.tf32.f32 "
        "{%0,%1,%2,%3},{%4,%5,%6,%7},{%8,%9},{%0,%1,%2,%3};"
        : "+f"(c[0]), "+f"(c[1]), "+f"(c[2]), "+f"(c[3])
        : "r"(a[0]), "r"(a[1]), "r"(a[2]), "r"(a[3]), "r"(b[0]), "r"(b[1]));
}

__device__ __forceinline__ void cp16(void* smem, const void* g) {
    unsigned s = (unsigned)__cvta_generic_to_shared(smem);
    asm volatile("cp.async.ca.shared.global [%0], [%1], 16;" :: "r"(s), "l"(g));
}
__device__ __forceinline__ void cp_commit() { asm volatile("cp.async.commit_group;"); }
__device__ __forceinline__ void cp_wait1()  { asm volatile("cp.async.wait_group 1;"); }
__device__ __forceinline__ void cp_wait0()  { asm volatile("cp.async.wait_group 0;"); }

// ---------------- tf32 pre-conversion (elementwise) ----------------
__global__ __launch_bounds__(256) void conv_tf32_kernel(const float4* __restrict__ src,
                                                        float4* __restrict__ dst, int n4) {
    int i = blockIdx.x * 256 + threadIdx.x;
    if (i < n4) {
        float4 v = src[i];
        v.x = tf32r(v.x); v.y = tf32r(v.y); v.z = tf32r(v.z); v.w = tf32r(v.w);
        dst[i] = v;
    }
}

// =======================================================================
// tf32 GEMM, cp.async double-buffered:  C[M,N] = A[M,K] * W[N,K]^T + bias
// BM=BN=128, BK=32, 256 threads = 8 warps (2x4), warp tile 64x32
// Operands MUST be pre-rounded to tf32.
// =======================================================================
#define GBM 128
#define GBN 128
#define GBK 32
#define LDS_STRIDE 36
#define GSTAGE (GBM*LDS_STRIDE)           // floats per operand per stage
#define GEMM_SMEM (4*GSTAGE*4)            // 73728 bytes

__global__ __launch_bounds__(256) void gemm_tf32_kernel(const float* __restrict__ A,
                                                        const float* __restrict__ W,
                                                        const float* __restrict__ bias,
                                                        float* __restrict__ out,
                                                        int mode) {
    extern __shared__ float gsm[];
    float* As = gsm;                 // [2][GSTAGE]
    float* Bs = gsm + 2*GSTAGE;      // [2][GSTAGE]

    const int tid  = threadIdx.x;
    const int warp = tid >> 5;
    const int wr   = warp >> 2;
    const int wc   = warp & 3;
    const int lane = tid & 31;
    const int gid  = lane >> 2;
    const int tidg = lane & 3;

    const int m0 = blockIdx.y * GBM;
    const int n0 = blockIdx.x * GBN;

    const int crow = tid >> 3;         // 0..31
    const int ccol = (tid & 7) * 4;    // 0..28

    float acc[4][4][4];
#pragma unroll
    for (int mi = 0; mi < 4; ++mi)
#pragma unroll
        for (int ni = 0; ni < 4; ++ni)
#pragma unroll
            for (int r = 0; r < 4; ++r) acc[mi][ni][r] = 0.f;

    const int NS = HIDDEN / GBK;       // 36 stages

    // stage loader
    auto load_stage = [&](int s) {
        float* dA = As + (s & 1) * GSTAGE;
        float* dB = Bs + (s & 1) * GSTAGE;
        const int kt = s * GBK;
#pragma unroll
        for (int p = 0; p < 4; ++p) {
            const int row = crow + p * 32;
            cp16(&dA[row * LDS_STRIDE + ccol], A + (size_t)(m0 + row) * HIDDEN + kt + ccol);
            cp16(&dB[row * LDS_STRIDE + ccol], W + (size_t)(n0 + row) * HIDDEN + kt + ccol);
        }
    };

    load_stage(0);
    cp_commit();

    for (int s = 0; s < NS; ++s) {
        if (s + 1 < NS) load_stage(s + 1);
        cp_commit();
        if (s + 1 < NS) cp_wait1(); else cp_wait0();
        __syncthreads();

        const float* cA = As + (s & 1) * GSTAGE;
        const float* cB = Bs + (s & 1) * GSTAGE;
#pragma unroll
        for (int ks = 0; ks < GBK / 8; ++ks) {
            unsigned a[4][4];
#pragma unroll
            for (int mi = 0; mi < 4; ++mi) {
                const int base = (wr * 64 + mi * 16 + gid) * LDS_STRIDE + ks * 8 + tidg;
                a[mi][0] = __float_as_uint(cA[base]);
                a[mi][1] = __float_as_uint(cA[base + 8 * LDS_STRIDE]);
                a[mi][2] = __float_as_uint(cA[base + 4]);
                a[mi][3] = __float_as_uint(cA[base + 8 * LDS_STRIDE + 4]);
            }
            unsigned b[4][2];
#pragma unroll
            for (int ni = 0; ni < 4; ++ni) {
                const int base = (wc * 32 + ni * 8 + gid) * LDS_STRIDE + ks * 8 + tidg;
                b[ni][0] = __float_as_uint(cB[base]);
                b[ni][1] = __float_as_uint(cB[base + 4]);
            }
#pragma unroll
            for (int mi = 0; mi < 4; ++mi)
#pragma unroll
                for (int ni = 0; ni < 4; ++ni)
                    mma_tf32(acc[mi][ni], a[mi], b[ni]);
        }
        __syncthreads();
    }

    // ---------------- epilogue ----------------
    if (mode == 0) {
        const int which = n0 / HIDDEN;
        float* dst = (which == 0) ? g_q : (which == 1) ? g_k : g_v;
#pragma unroll
        for (int mi = 0; mi < 4; ++mi)
#pragma unroll
            for (int ni = 0; ni < 4; ++ni)
#pragma unroll
                for (int cr = 0; cr < 4; ++cr) {
                    const int row = m0 + wr * 64 + mi * 16 + gid + (cr >> 1) * 8;
                    const int col = n0 + wc * 32 + ni * 8 + 2 * tidg + (cr & 1);
                    const int rem = col - which * HIDDEN;
                    const int h   = rem / HD;
                    const int d   = rem - h * HD;
                    const int bi  = row >> 10;
                    const int si  = row & (SEQ - 1);
                    float val = acc[mi][ni][cr] + bias[col];
                    if (which == 2) val = tf32r(val);   // v feeds mma directly
                    dst[(((size_t)(bi * HEADS + h)) * SEQ + si) * HD + d] = val;
                }
    } else {
#pragma unroll
        for (int mi = 0; mi < 4; ++mi)
#pragma unroll
            for (int ni = 0; ni < 4; ++ni)
#pragma unroll
                for (int cr = 0; cr < 4; ++cr) {
                    const int row = m0 + wr * 64 + mi * 16 + gid + (cr >> 1) * 8;
                    const int col = n0 + wc * 32 + ni * 8 + 2 * tidg + (cr & 1);
                    out[(size_t)row * HIDDEN + col] = acc[mi][ni][cr] + bias[col];
                }
    }
}

// ---------------- RMSNorm over head_dim=72 (outputs tf32-rounded) ----------------
__global__ __launch_bounds__(256) void rmsnorm_kernel(int sel, const float* __restrict__ gamma) {
    float* t = sel ? g_k : g_q;
    const int row  = blockIdx.x * 8 + (threadIdx.x >> 5);
    const int lane = threadIdx.x & 31;
    float* p = t + (size_t)row * HD;
    float v0 = p[lane];
    float v1 = p[32 + lane];
    float v2 = (lane < 8) ? p[64 + lane] : 0.f;
    float ss = v0*v0 + v1*v1 + v2*v2;
#pragma unroll
    for (int o = 16; o; o >>= 1) ss += __shfl_xor_sync(0xffffffffu, ss, o);
    const float rs = rsqrtf(ss * (1.0f/72.0f) + RMS_EPS);
    p[lane]      = tf32r(v0 * rs * gamma[lane]);
    p[32 + lane] = tf32r(v1 * rs * gamma[32 + lane]);
    if (lane < 8) p[64 + lane] = tf32r(v2 * rs * gamma[64 + lane]);
}

// =======================================================================
// FA2-style attention on tensor cores (tf32 mma m16n8k8)
// 1 CTA = (b, h, 64 q rows); 4 warps, each owns 16 q rows.
// smem strides: Q/K/P = 76 (conflict-free for g-indexed row loads),
//               V = 72 (conflict-free for V^T B-fragment loads).
// =======================================================================
#define QKP_STR 76
#define VS_STR  72
#define ATTN_SMEM ((3*64*QKP_STR + 64*VS_STR)*4)   // 76800 bytes

__global__ __launch_bounds__(128) void attn_mma_kernel() {
    extern __shared__ float sm[];
    float* Qs = sm;                          // 64 x 76
    float* Ks = Qs + 64*QKP_STR;             // 64 x 76
    float* Ps = Ks + 64*QKP_STR;             // 64 x 76 (64 cols used)
    float* Vs = Ps + 64*QKP_STR;             // 64 x 72

    const int qt = blockIdx.x;
    const int h  = blockIdx.y;
    const int b  = blockIdx.z;
    const int tid  = threadIdx.x;
    const int warp = tid >> 5;
    const int lane = tid & 31;
    const int g    = lane >> 2;    // 0..7
    const int t    = lane & 3;     // 0..3
    const int mrow = warp * 16;

    const size_t head_base = ((size_t)(b*HEADS + h)) * SEQ * HD;
    const size_t q_base = head_base + (size_t)qt * 64 * HD;

    // load Q tile (already tf32-rounded by rmsnorm); raw values, scale applied on scores
#pragma unroll
    for (int i4 = tid; i4 < 64*18; i4 += 128) {
        const int row = i4 / 18, c4 = i4 - row*18;
        *(float4*)&Qs[row*QKP_STR + c4*4] = *(const float4*)&g_q[q_base + row*HD + c4*4];
    }

    float o[9][4];
#pragma unroll
    for (int n = 0; n < 9; ++n)
#pragma unroll
        for (int r = 0; r < 4; ++r) o[n][r] = 0.f;
    float m0 = -INFINITY, m1 = -INFINITY, l0 = 0.f, l1 = 0.f;

    for (int kt = 0; kt < SEQ/64; ++kt) {
        __syncthreads();
        const size_t kv_base = head_base + (size_t)kt * 64 * HD;
#pragma unroll
        for (int i4 = tid; i4 < 64*18; i4 += 128) {
            const int row = i4 / 18, c4 = i4 - row*18;
            *(float4*)&Ks[row*QKP_STR + c4*4] = *(const float4*)&g_k[kv_base + row*HD + c4*4];
            *(float4*)&Vs[row*VS_STR  + c4*4] = *(const float4*)&g_v[kv_base + row*HD + c4*4];
        }
        __syncthreads();

        // ---- scores S[16x64] = Q_warp @ K^T ----
        float c[8][4];
#pragma unroll
        for (int n = 0; n < 8; ++n)
#pragma unroll
            for (int r = 0; r < 4; ++r) c[n][r] = 0.f;

#pragma unroll
        for (int ks = 0; ks < 9; ++ks) {
            unsigned a[4];
            a[0] = __float_as_uint(Qs[(mrow + g    )*QKP_STR + ks*8 + t    ]);
            a[1] = __float_as_uint(Qs[(mrow + g + 8)*QKP_STR + ks*8 + t    ]);
            a[2] = __float_as_uint(Qs[(mrow + g    )*QKP_STR + ks*8 + t + 4]);
            a[3] = __float_as_uint(Qs[(mrow + g + 8)*QKP_STR + ks*8 + t + 4]);
#pragma unroll
            for (int n = 0; n < 8; ++n) {
                unsigned bb[2];
                bb[0] = __float_as_uint(Ks[(n*8 + g)*QKP_STR + ks*8 + t    ]);
                bb[1] = __float_as_uint(Ks[(n*8 + g)*QKP_STR + ks*8 + t + 4]);
                mma_tf32(c[n], a, bb);
            }
        }

        // scale
#pragma unroll
        for (int n = 0; n < 8; ++n)
#pragma unroll
            for (int r = 0; r < 4; ++r) c[n][r] *= QSCALE;

        // ---- online softmax (rows g and g+8) ----
        float mx0 = -INFINITY, mx1 = -INFINITY;
#pragma unroll
        for (int n = 0; n < 8; ++n) {
            mx0 = fmaxf(mx0, fmaxf(c[n][0], c[n][1]));
            mx1 = fmaxf(mx1, fmaxf(c[n][2], c[n][3]));
        }
        mx0 = fmaxf(mx0, __shfl_xor_sync(0xffffffffu, mx0, 1));
        mx0 = fmaxf(mx0, __shfl_xor_sync(0xffffffffu, mx0, 2));
        mx1 = fmaxf(mx1, __shfl_xor_sync(0xffffffffu, mx1, 1));
        mx1 = fmaxf(mx1, __shfl_xor_sync(0xffffffffu, mx1, 2));

        const float m0n = fmaxf(m0, mx0);
        const float m1n = fmaxf(m1, mx1);
        const float fac0 = __expf(m0 - m0n);
        const float fac1 = __expf(m1 - m1n);

        float sum0 = 0.f, sum1 = 0.f;
#pragma unroll
        for (int n = 0; n < 8; ++n) {
            float p0 = __expf(c[n][0] - m0n);
            float p1 = __expf(c[n][1] - m0n);
            float p2 = __expf(c[n][2] - m1n);
            float p3 = __expf(c[n][3] - m1n);
            sum0 += p0 + p1;
            sum1 += p2 + p3;
            float2 lo = make_float2(__uint_as_float(f2tf32(p0)), __uint_as_float(f2tf32(p1)));
            float2 hi = make_float2(__uint_as_float(f2tf32(p2)), __uint_as_float(f2tf32(p3)));
            *(float2*)&Ps[(mrow + g    )*QKP_STR + n*8 + 2*t] = lo;
            *(float2*)&Ps[(mrow + g + 8)*QKP_STR + n*8 + 2*t] = hi;
        }
        sum0 += __shfl_xor_sync(0xffffffffu, sum0, 1);
        sum0 += __shfl_xor_sync(0xffffffffu, sum0, 2);
        sum1 += __shfl_xor_sync(0xffffffffu, sum1, 1);
        sum1 += __shfl_xor_sync(0xffffffffu, sum1, 2);

        l0 = l0 * fac0 + sum0;  m0 = m0n;
        l1 = l1 * fac1 + sum1;  m1 = m1n;

#pragma unroll
        for (int n = 0; n < 9; ++n) {
            o[n][0] *= fac0; o[n][1] *= fac0;
            o[n][2] *= fac1; o[n][3] *= fac1;
        }

        __syncwarp();   // P visible warp-wide before A-fragment loads

        // ---- O[16x72] += P[16x64] @ V[64x72] ----
#pragma unroll
        for (int ks = 0; ks < 8; ++ks) {
            unsigned a[4];
            a[0] = __float_as_uint(Ps[(mrow + g    )*QKP_STR + ks*8 + t    ]);
            a[1] = __float_as_uint(Ps[(mrow + g + 8)*QKP_STR + ks*8 + t    ]);
            a[2] = __float_as_uint(Ps[(mrow + g    )*QKP_STR + ks*8 + t + 4]);
            a[3] = __float_as_uint(Ps[(mrow + g + 8)*QKP_STR + ks*8 + t + 4]);
#pragma unroll
            for (int n = 0; n < 9; ++n) {
                unsigned bb[2];
                bb[0] = __float_as_uint(Vs[(ks*8 + t    )*VS_STR + n*8 + g]);
                bb[1] = __float_as_uint(Vs[(ks*8 + t + 4)*VS_STR + n*8 + g]);
                mma_tf32(o[n], a, bb);
            }
        }
    }

    // ---- epilogue: normalize, round to tf32 (feeds proj GEMM), store ----
    const float inv0 = 1.0f / l0;
    const float inv1 = 1.0f / l1;
    const int q0 = qt*64 + mrow + g;
    const int q1 = q0 + 8;
    float* base0 = g_attn + (((size_t)(b*SEQ + q0))*HEADS + h)*HD;
    float* base1 = g_attn + (((size_t)(b*SEQ + q1))*HEADS + h)*HD;
#pragma unroll
    for (int n = 0; n < 9; ++n) {
        const int d = n*8 + 2*t;
        float2 lo = make_float2(__uint_as_float(f2tf32(o[n][0]*inv0)),
                                __uint_as_float(f2tf32(o[n][1]*inv0)));
        float2 hi = make_float2(__uint_as_float(f2tf32(o[n][2]*inv1)),
                                __uint_as_float(f2tf32(o[n][3]*inv1)));
        *(float2*)&base0[d] = lo;
        *(float2*)&base1[d] = hi;
    }
}

// ---------------- launch ----------------
extern "C" void kernel_launch(void* const* d_in, const int* in_sizes, int n_in,
                              void* d_out, int out_size) {
    const float* x      = (const float*)d_in[0];
    const float* w_qkv  = (const float*)d_in[1];
    const float* b_qkv  = (const float*)d_in[2];
    const float* q_gamma= (const float*)d_in[3];
    const float* k_gamma= (const float*)d_in[4];
    const float* w_proj = (const float*)d_in[5];
    const float* b_proj = (const float*)d_in[6];
    float* out = (float*)d_out;

    static int attr_done = 0;
    cudaFuncSetAttribute(attn_mma_kernel, cudaFuncAttributeMaxDynamicSharedMemorySize, ATTN_SMEM);
    cudaFuncSetAttribute(gemm_tf32_kernel, cudaFuncAttributeMaxDynamicSharedMemorySize, GEMM_SMEM);
    (void)attr_done;

    float *xt, *wq, *wp, *attn_ptr;
    cudaGetSymbolAddress((void**)&xt, g_xt);
    cudaGetSymbolAddress((void**)&wq, g_wq);
    cudaGetSymbolAddress((void**)&wp, g_wp);
    cudaGetSymbolAddress((void**)&attn_ptr, g_attn);

    {   // pre-round GEMM operands to tf32
        int n4x = M_TOT*HIDDEN/4, n4q = N_QKV*HIDDEN/4, n4p = HIDDEN*HIDDEN/4;
        conv_tf32_kernel<<<(n4x+255)/256, 256>>>((const float4*)x, (float4*)xt, n4x);
        conv_tf32_kernel<<<(n4q+255)/256, 256>>>((const float4*)w_qkv, (float4*)wq, n4q);
        conv_tf32_kernel<<<(n4p+255)/256, 256>>>((const float4*)w_proj, (float4*)wp, n4p);
    }
    {   // QKV projection
        dim3 grid(N_QKV / GBN, M_TOT / GBM);   // (27, 128)
        gemm_tf32_kernel<<<grid, 256, GEMM_SMEM>>>(xt, wq, b_qkv, nullptr, 0);
    }
    {   // RMSNorm q, k
        const int rows = BATCH*HEADS*SEQ;
        rmsnorm_kernel<<<rows/8, 256>>>(0, q_gamma);
        rmsnorm_kernel<<<rows/8, 256>>>(1, k_gamma);
    }
    {   // attention (tensor cores)
        dim3 grid(SEQ/64, HEADS, BATCH);       // (16,16,16)
        attn_mma_kernel<<<grid, 128, ATTN_SMEM>>>();
    }
    {   // output projection
        dim3 grid(HIDDEN / GBN, M_TOT / GBM);  // (9, 128)
        gemm_tf32_kernel<<<grid, 256, GEMM_SMEM>>>(attn_ptr, wp, b_proj, out, 1);
    }
}

// round 5
// speedup vs baseline: 16.4570x; 2.1312x over previous
#include <cuda_runtime.h>
#include <cuda_fp16.h>
#include <math.h>

#define HIDDEN 1152
#define HEADS  16
#define HD     72
#define BATCH  16
#define SEQ    1024
#define M_TOT  (BATCH*SEQ)
#define N_QKV  (3*HIDDEN)
#define QSCALE 0.11785113f
#define RMS_EPS 1.1920928955078125e-07f

// ---------------- scratch ----------------
__device__ __align__(256) __half g_qh[(size_t)BATCH*HEADS*SEQ*HD];
__device__ __align__(256) __half g_kh[(size_t)BATCH*HEADS*SEQ*HD];
__device__ __align__(256) __half g_vh[(size_t)BATCH*HEADS*SEQ*HD];
__device__ __align__(256) __half g_ah[(size_t)M_TOT*HIDDEN];     // attn out
__device__ __align__(256) __half g_xh[(size_t)M_TOT*HIDDEN];
__device__ __align__(256) __half g_wqh[(size_t)N_QKV*HIDDEN];
__device__ __align__(256) __half g_wph[(size_t)HIDDEN*HIDDEN];

// ---------------- helpers ----------------
__device__ __forceinline__ unsigned h2u(__half2 h) {
    unsigned u;
    asm("mov.b32 %0, %1;" : "=r"(u) : "r"(*(unsigned*)&h));
    return u;
}
__device__ __forceinline__ unsigned sptr(const void* p) {
    return (unsigned)__cvta_generic_to_shared(p);
}
__device__ __forceinline__ void ldsm4(unsigned r[4], const void* p) {
    asm volatile("ldmatrix.sync.aligned.m8n8.x4.shared.b16 {%0,%1,%2,%3},[%4];"
                 : "=r"(r[0]), "=r"(r[1]), "=r"(r[2]), "=r"(r[3]) : "r"(sptr(p)));
}
__device__ __forceinline__ void ldsm4t(unsigned r[4], const void* p) {
    asm volatile("ldmatrix.sync.aligned.m8n8.x4.trans.shared.b16 {%0,%1,%2,%3},[%4];"
                 : "=r"(r[0]), "=r"(r[1]), "=r"(r[2]), "=r"(r[3]) : "r"(sptr(p)));
}
__device__ __forceinline__ void ldsm2t(unsigned r[2], const void* p) {
    asm volatile("ldmatrix.sync.aligned.m8n8.x2.trans.shared.b16 {%0,%1},[%2];"
                 : "=r"(r[0]), "=r"(r[1]) : "r"(sptr(p)));
}
__device__ __forceinline__ void mma16816(float c[4], const unsigned a[4],
                                         unsigned b0, unsigned b1) {
    asm volatile(
        "mma.sync.aligned.m16n8k16.row.col.f32.f16.f16.f32 "
        "{%0,%1,%2,%3},{%4,%5,%6,%7},{%8,%9},{%0,%1,%2,%3};"
        : "+f"(c[0]), "+f"(c[1]), "+f"(c[2]), "+f"(c[3])
        : "r"(a[0]), "r"(a[1]), "r"(a[2]), "r"(a[3]), "r"(b0), "r"(b1));
}
__device__ __forceinline__ void cp16(void* smem, const void* g) {
    asm volatile("cp.async.ca.shared.global [%0], [%1], 16;" :: "r"(sptr(smem)), "l"(g));
}
__device__ __forceinline__ void cp_commit() { asm volatile("cp.async.commit_group;"); }
__device__ __forceinline__ void cp_wait1()  { asm volatile("cp.async.wait_group 1;"); }
__device__ __forceinline__ void cp_wait2()  { asm volatile("cp.async.wait_group 2;"); }

// ---------------- fp32 -> fp16 conversion ----------------
__global__ __launch_bounds__(256) void conv_h_kernel(const float4* __restrict__ src,
                                                     uint4* __restrict__ dst, int n8) {
    int i = blockIdx.x * 256 + threadIdx.x;
    if (i < n8) {
        float4 f0 = src[2*i], f1 = src[2*i+1];
        uint4 o;
        o.x = h2u(__floats2half2_rn(f0.x, f0.y));
        o.y = h2u(__floats2half2_rn(f0.z, f0.w));
        o.z = h2u(__floats2half2_rn(f1.x, f1.y));
        o.w = h2u(__floats2half2_rn(f1.z, f1.w));
        dst[i] = o;
    }
}

// =======================================================================
// fp16 GEMM: C[M,N] = A[M,K] * W[N,K]^T + bias.  BM=256 BN=128 BK=64,
// 256 thr = 8 warps (4x2), warp 64x64, 3-stage cp.async, XOR-swizzled smem.
// =======================================================================
#define GA_ST 16384   // halves per A stage (256*64)
#define GB_ST 8192    // halves per B stage (128*64)
#define GEMM_SMEM (3*(GA_ST+GB_ST)*2)   // 147456 bytes

__global__ __launch_bounds__(256) void gemm_f16_kernel(const __half* __restrict__ A,
                                                       const __half* __restrict__ W,
                                                       const float* __restrict__ bias,
                                                       float* __restrict__ out,
                                                       int mode) {
    extern __shared__ __half hsm[];
    __half* As = hsm;
    __half* Bs = hsm + 3*GA_ST;

    const int tid  = threadIdx.x;
    const int warp = tid >> 5;
    const int wr   = warp >> 1;     // 0..3
    const int wc   = warp & 1;      // 0..1
    const int lane = tid & 31;
    const int g    = lane >> 2;
    const int t    = lane & 3;

    const int m0 = blockIdx.y * 256;
    const int n0 = blockIdx.x * 128;

    float acc[4][8][4];
#pragma unroll
    for (int mi = 0; mi < 4; ++mi)
#pragma unroll
        for (int ni = 0; ni < 8; ++ni)
#pragma unroll
            for (int r = 0; r < 4; ++r) acc[mi][ni][r] = 0.f;

    const int NS = HIDDEN / 64;   // 18

    auto load_stage = [&](int s) {
        __half* dA = As + (s % 3) * GA_ST;
        __half* dB = Bs + (s % 3) * GB_ST;
        const int kt = s * 64;
#pragma unroll
        for (int p = 0; p < 8; ++p) {
            const int idx = tid + p * 256;
            const int row = idx >> 3, c = idx & 7, pc = c ^ (row & 7);
            cp16(dA + (row*8 + pc)*8, A + (size_t)(m0 + row) * HIDDEN + kt + c*8);
        }
#pragma unroll
        for (int p = 0; p < 4; ++p) {
            const int idx = tid + p * 256;
            const int row = idx >> 3, c = idx & 7, pc = c ^ (row & 7);
            cp16(dB + (row*8 + pc)*8, W + (size_t)(n0 + row) * HIDDEN + kt + c*8);
        }
    };

    load_stage(0); cp_commit();
    load_stage(1); cp_commit();

    const int a_rin  = lane & 15;
    const int a_koff = lane >> 4;            // 0/1
    const int b_nin  = (lane & 7) + ((lane >> 4) << 3);
    const int b_koff = (lane >> 3) & 1;

    for (int s = 0; s < NS; ++s) {
        if (s + 2 < NS) load_stage(s + 2);
        cp_commit();
        cp_wait2();
        __syncthreads();
        const __half* cA = As + (s % 3) * GA_ST;
        const __half* cB = Bs + (s % 3) * GB_ST;
#pragma unroll
        for (int ks = 0; ks < 4; ++ks) {
            unsigned a[4][4];
#pragma unroll
            for (int mi = 0; mi < 4; ++mi) {
                const int row = wr*64 + mi*16 + a_rin;
                const int pc  = (ks*2 + a_koff) ^ (row & 7);
                ldsm4(a[mi], cA + (row*8 + pc)*8);
            }
            unsigned bf[8][2];
#pragma unroll
            for (int p = 0; p < 4; ++p) {
                const int row = wc*64 + p*16 + b_nin;
                const int pc  = (ks*2 + b_koff) ^ (row & 7);
                unsigned q[4];
                ldsm4(q, cB + (row*8 + pc)*8);
                bf[2*p][0] = q[0]; bf[2*p][1] = q[1];
                bf[2*p+1][0] = q[2]; bf[2*p+1][1] = q[3];
            }
#pragma unroll
            for (int mi = 0; mi < 4; ++mi)
#pragma unroll
                for (int ni = 0; ni < 8; ++ni)
                    mma16816(acc[mi][ni], a[mi], bf[ni][0], bf[ni][1]);
        }
        __syncthreads();
    }

    // ---------------- epilogue ----------------
    if (mode == 0) {
        const int which = n0 / HIDDEN;
        __half* dst = (which == 0) ? g_qh : (which == 1) ? g_kh : g_vh;
#pragma unroll
        for (int mi = 0; mi < 4; ++mi)
#pragma unroll
            for (int ni = 0; ni < 8; ++ni) {
                const int col = n0 + wc*64 + ni*8 + 2*t;
                const int rem = col - which * HIDDEN;
                const int h   = rem / HD;
                const int d   = rem - h * HD;
                const float b0 = bias[col], b1 = bias[col + 1];
#pragma unroll
                for (int half_ = 0; half_ < 2; ++half_) {
                    const int row = m0 + wr*64 + mi*16 + g + half_*8;
                    const int bi  = row >> 10, si = row & (SEQ - 1);
                    __half2 v = __floats2half2_rn(acc[mi][ni][2*half_] + b0,
                                                  acc[mi][ni][2*half_+1] + b1);
                    *(__half2*)&dst[(((size_t)(bi*HEADS + h))*SEQ + si)*HD + d] = v;
                }
            }
    } else {
#pragma unroll
        for (int mi = 0; mi < 4; ++mi)
#pragma unroll
            for (int ni = 0; ni < 8; ++ni) {
                const int col = n0 + wc*64 + ni*8 + 2*t;
                const float b0 = bias[col], b1 = bias[col + 1];
#pragma unroll
                for (int half_ = 0; half_ < 2; ++half_) {
                    const int row = m0 + wr*64 + mi*16 + g + half_*8;
                    float2 v = make_float2(acc[mi][ni][2*half_] + b0,
                                           acc[mi][ni][2*half_+1] + b1);
                    *(float2*)&out[(size_t)row * HIDDEN + col] = v;
                }
            }
    }
}

// ---------------- RMSNorm (half in/out), scale folded ----------------
__global__ __launch_bounds__(256) void rmsnorm_h_kernel(__half* __restrict__ tp,
                                                        const float* __restrict__ gamma,
                                                        float scale) {
    const int row  = blockIdx.x * 8 + (threadIdx.x >> 5);
    const int lane = threadIdx.x & 31;
    __half* p = tp + (size_t)row * HD;
    float v0 = __half2float(p[lane]);
    float v1 = __half2float(p[32 + lane]);
    float v2 = (lane < 8) ? __half2float(p[64 + lane]) : 0.f;
    float ss = v0*v0 + v1*v1 + v2*v2;
#pragma unroll
    for (int o = 16; o; o >>= 1) ss += __shfl_xor_sync(0xffffffffu, ss, o);
    const float rs = rsqrtf(ss * (1.0f/72.0f) + RMS_EPS) * scale;
    p[lane]      = __float2half(v0 * rs * gamma[lane]);
    p[32 + lane] = __float2half(v1 * rs * gamma[32 + lane]);
    if (lane < 8) p[64 + lane] = __float2half(v2 * rs * gamma[64 + lane]);
}

// =======================================================================
// fp16 flash attention: CTA = (b,h,128 q rows), 8 warps x 16 rows,
// K/V double-buffered cp.async, P stays in registers (C-frag -> A-frag).
// Rows padded 72 -> 80 halves (chunk 9 zeroed); chunks 0..7 XOR-swizzled.
// =======================================================================
#define AQ_H (128*80)
#define AK_H (2*64*80)
#define ATTN_SMEM ((AQ_H + 2*AK_H)*2)    // 61440 bytes

__global__ __launch_bounds__(256, 2) void attn_f16_kernel() {
    extern __shared__ __half asm_[];
    __half* Qs = asm_;               // 128 x 80
    __half* Ks = Qs + AQ_H;          // 2 x 64 x 80
    __half* Vs = Ks + AK_H;          // 2 x 64 x 80

    const int qt = blockIdx.x;       // 0..7
    const int h  = blockIdx.y;
    const int b  = blockIdx.z;
    const int tid  = threadIdx.x;
    const int warp = tid >> 5;
    const int lane = tid & 31;
    const int g    = lane >> 2;
    const int t    = lane & 3;

    const size_t head_base = ((size_t)(b*HEADS + h)) * SEQ * HD;
    const __half* gQ = g_qh + head_base + (size_t)qt * 128 * HD;
    const __half* gK = g_kh + head_base;
    const __half* gV = g_vh + head_base;

    // zero pad chunk 9 of every row (Q:128, K:2x64, V:2x64 rows)
    for (int r = tid; r < 384; r += 256) {
        __half* base = (r < 128) ? Qs : (r < 256) ? Ks : Vs;
        const int rr = r & 127;
        *(uint4*)&base[(rr*10 + 9)*8] = make_uint4(0,0,0,0);
    }
    // Q load
    for (int idx = tid; idx < 1152; idx += 256) {
        const int row = idx / 9, c = idx - row*9;
        const int pc = (c < 8) ? (c ^ (row & 7)) : 8;
        cp16(Qs + (row*10 + pc)*8, gQ + row*HD + c*8);
    }
    auto load_kv = [&](int kt) {
        __half* Kb = Ks + (kt & 1) * 64*80;
        __half* Vb = Vs + (kt & 1) * 64*80;
        const size_t base = (size_t)kt * 64 * HD;
        for (int idx = tid; idx < 1152; idx += 256) {
            const int arr = idx >= 576;
            const int rem = idx - 576*arr;
            const int row = rem / 9, c = rem - row*9;
            const int pc = (c < 8) ? (c ^ (row & 7)) : 8;
            if (arr) cp16(Vb + (row*10 + pc)*8, gV + base + row*HD + c*8);
            else     cp16(Kb + (row*10 + pc)*8, gK + base + row*HD + c*8);
        }
    };
    load_kv(0);
    cp_commit();

    float o[9][4];
#pragma unroll
    for (int n = 0; n < 9; ++n)
#pragma unroll
        for (int r = 0; r < 4; ++r) o[n][r] = 0.f;
    float m0 = -INFINITY, m1 = -INFINITY, l0 = 0.f, l1 = 0.f;

    const int a_rin  = lane & 15;
    const int a_koff = lane >> 4;
    const int b_nin  = (lane & 7) + ((lane >> 4) << 3);
    const int b_koff = (lane >> 3) & 1;
    const int v_sin  = (lane & 7) + ((lane >> 3) & 1) * 8;
    const int v_doff = lane >> 4;    // 0/1 (d-chunk selector for x4 trans)

    for (int kt = 0; kt < SEQ/64; ++kt) {
        if (kt + 1 < SEQ/64) load_kv(kt + 1);
        cp_commit();
        cp_wait1();
        __syncthreads();
        const __half* Kb = Ks + (kt & 1) * 64*80;
        const __half* Vb = Vs + (kt & 1) * 64*80;

        // ---- S = Q @ K^T (5 k16 slices over padded d=80) ----
        float c[8][4];
#pragma unroll
        for (int n = 0; n < 8; ++n)
#pragma unroll
            for (int r = 0; r < 4; ++r) c[n][r] = 0.f;
#pragma unroll
        for (int ks = 0; ks < 5; ++ks) {
            unsigned aq[4];
            {
                const int row = warp*16 + a_rin;
                const int ch  = 2*ks + a_koff;
                const int pc  = (ch < 8) ? (ch ^ (row & 7)) : ch;
                ldsm4(aq, Qs + (row*10 + pc)*8);
            }
#pragma unroll
            for (int p = 0; p < 4; ++p) {
                const int row = p*16 + b_nin;
                const int ch  = 2*ks + b_koff;
                const int pc  = (ch < 8) ? (ch ^ (row & 7)) : ch;
                unsigned q[4];
                ldsm4(q, Kb + (row*10 + pc)*8);
                mma16816(c[2*p],   aq, q[0], q[1]);
                mma16816(c[2*p+1], aq, q[2], q[3]);
            }
        }

        // ---- online softmax ----
        float mx0 = -INFINITY, mx1 = -INFINITY;
#pragma unroll
        for (int n = 0; n < 8; ++n) {
            mx0 = fmaxf(mx0, fmaxf(c[n][0], c[n][1]));
            mx1 = fmaxf(mx1, fmaxf(c[n][2], c[n][3]));
        }
        mx0 = fmaxf(mx0, __shfl_xor_sync(0xffffffffu, mx0, 1));
        mx0 = fmaxf(mx0, __shfl_xor_sync(0xffffffffu, mx0, 2));
        mx1 = fmaxf(mx1, __shfl_xor_sync(0xffffffffu, mx1, 1));
        mx1 = fmaxf(mx1, __shfl_xor_sync(0xffffffffu, mx1, 2));
        const float m0n = fmaxf(m0, mx0), m1n = fmaxf(m1, mx1);
        const float fac0 = __expf(m0 - m0n), fac1 = __expf(m1 - m1n);

        float sum0 = 0.f, sum1 = 0.f;
#pragma unroll
        for (int n = 0; n < 8; ++n) {
            c[n][0] = __expf(c[n][0] - m0n);
            c[n][1] = __expf(c[n][1] - m0n);
            c[n][2] = __expf(c[n][2] - m1n);
            c[n][3] = __expf(c[n][3] - m1n);
            sum0 += c[n][0] + c[n][1];
            sum1 += c[n][2] + c[n][3];
        }
        sum0 += __shfl_xor_sync(0xffffffffu, sum0, 1);
        sum0 += __shfl_xor_sync(0xffffffffu, sum0, 2);
        sum1 += __shfl_xor_sync(0xffffffffu, sum1, 1);
        sum1 += __shfl_xor_sync(0xffffffffu, sum1, 2);
        l0 = l0 * fac0 + sum0;  m0 = m0n;
        l1 = l1 * fac1 + sum1;  m1 = m1n;

        // repack P C-frags -> PV A-frags (registers only)
        unsigned pa[4][4];
#pragma unroll
        for (int k2 = 0; k2 < 4; ++k2) {
            pa[k2][0] = h2u(__floats2half2_rn(c[2*k2][0],   c[2*k2][1]));
            pa[k2][1] = h2u(__floats2half2_rn(c[2*k2][2],   c[2*k2][3]));
            pa[k2][2] = h2u(__floats2half2_rn(c[2*k2+1][0], c[2*k2+1][1]));
            pa[k2][3] = h2u(__floats2half2_rn(c[2*k2+1][2], c[2*k2+1][3]));
        }
#pragma unroll
        for (int n = 0; n < 9; ++n) {
            o[n][0] *= fac0; o[n][1] *= fac0;
            o[n][2] *= fac1; o[n][3] *= fac1;
        }

        // ---- O += P @ V  (V via ldmatrix.trans) ----
#pragma unroll
        for (int k2 = 0; k2 < 4; ++k2) {
#pragma unroll
            for (int p2 = 0; p2 < 4; ++p2) {
                const int srow = k2*16 + v_sin;
                const int ch   = 2*p2 + v_doff;
                const int pc   = ch ^ (srow & 7);
                unsigned q[4];
                ldsm4t(q, Vb + (srow*10 + pc)*8);
                mma16816(o[2*p2],   pa[k2], q[0], q[1]);
                mma16816(o[2*p2+1], pa[k2], q[2], q[3]);
            }
            {   // ntile 8 (d 64..71), chunk 8 unswizzled
                const int srow = k2*16 + v_sin;
                unsigned q2[2];
                ldsm2t(q2, Vb + (srow*10 + 8)*8);
                mma16816(o[8], pa[k2], q2[0], q2[1]);
            }
        }
        __syncthreads();
    }

    // ---- epilogue ----
    const float inv0 = 1.0f / l0, inv1 = 1.0f / l1;
    const int q0 = qt*128 + warp*16 + g;
    __half* base0 = g_ah + ((size_t)(b*SEQ + q0)     * HIDDEN) + h*HD;
    __half* base1 = g_ah + ((size_t)(b*SEQ + q0 + 8) * HIDDEN) + h*HD;
#pragma unroll
    for (int n = 0; n < 9; ++n) {
        const int d = n*8 + 2*t;
        *(__half2*)&base0[d] = __floats2half2_rn(o[n][0]*inv0, o[n][1]*inv0);
        *(__half2*)&base1[d] = __floats2half2_rn(o[n][2]*inv1, o[n][3]*inv1);
    }
}

// ---------------- launch ----------------
extern "C" void kernel_launch(void* const* d_in, const int* in_sizes, int n_in,
                              void* d_out, int out_size) {
    const float* x      = (const float*)d_in[0];
    const float* w_qkv  = (const float*)d_in[1];
    const float* b_qkv  = (const float*)d_in[2];
    const float* q_gamma= (const float*)d_in[3];
    const float* k_gamma= (const float*)d_in[4];
    const float* w_proj = (const float*)d_in[5];
    const float* b_proj = (const float*)d_in[6];
    float* out = (float*)d_out;

    cudaFuncSetAttribute(gemm_f16_kernel, cudaFuncAttributeMaxDynamicSharedMemorySize, GEMM_SMEM);
    cudaFuncSetAttribute(attn_f16_kernel, cudaFuncAttributeMaxDynamicSharedMemorySize, ATTN_SMEM);

    __half *xh, *wqh, *wph, *ah, *qh, *kh;
    cudaGetSymbolAddress((void**)&xh,  g_xh);
    cudaGetSymbolAddress((void**)&wqh, g_wqh);
    cudaGetSymbolAddress((void**)&wph, g_wph);
    cudaGetSymbolAddress((void**)&ah,  g_ah);
    cudaGetSymbolAddress((void**)&qh,  g_qh);
    cudaGetSymbolAddress((void**)&kh,  g_kh);

    {   // fp32 -> fp16 conversions
        int n8x = M_TOT*HIDDEN/8, n8q = N_QKV*HIDDEN/8, n8p = HIDDEN*HIDDEN/8;
        conv_h_kernel<<<(n8x+255)/256, 256>>>((const float4*)x, (uint4*)xh, n8x);
        conv_h_kernel<<<(n8q+255)/256, 256>>>((const float4*)w_qkv, (uint4*)wqh, n8q);
        conv_h_kernel<<<(n8p+255)/256, 256>>>((const float4*)w_proj, (uint4*)wph, n8p);
    }
    {   // QKV projection
        dim3 grid(N_QKV/128, M_TOT/256);   // (27, 64)
        gemm_f16_kernel<<<grid, 256, GEMM_SMEM>>>(xh, wqh, b_qkv, nullptr, 0);
    }
    {   // RMSNorm (q gets 1/sqrt(hd) folded in)
        const int rows = BATCH*HEADS*SEQ;
        rmsnorm_h_kernel<<<rows/8, 256>>>(qh, q_gamma, QSCALE);
        rmsnorm_h_kernel<<<rows/8, 256>>>(kh, k_gamma, 1.0f);
    }
    {   // attention
        dim3 grid(SEQ/128, HEADS, BATCH);  // (8,16,16)
        attn_f16_kernel<<<grid, 256, ATTN_SMEM>>>();
    }
    {   // output projection
        dim3 grid(HIDDEN/128, M_TOT/256);  // (9, 64)
        gemm_f16_kernel<<<grid, 256, GEMM_SMEM>>>(ah, wph, b_proj, out, 1);
    }
}